// round 14
// baseline (speedup 1.0000x reference)
#include <cuda_runtime.h>
#include <cuda_bf16.h>
#include <cstdint>

// HeteLinear: out[n] = x[n] @ W[x_type[n]] + b[x_type[n]]
// N=262144, IN=OUT=128, T=8, fp32.
// Grouped GEMM on mma.sync HMMA bf16, 3-product bf16 hi/lo split.
// R14: consumer inner loop restructured for hi/lo FRAGMENT SHARING:
// one kk-loop loads a_hi/a_lo/b_hi/b_lo once (8 ldsm) and issues all 24 mma
// (hi*hi + hi*lo + lo*hi) -> 64 ldsm/warp instead of 96, and each kk's LDS
// latency is amortized over 192 cyc of tensor work. Producer pipeline,
// compaction, and epilogue are identical to the passing R13 (147.6us).

#define NMAX    262144
#define TT      8
#define DIM     128
#define TILE_M  64
#define GT      512
#define NB      256                 // compaction blocks
#define BT      256
#define PREPB   32                  // prep blocks appended to k_pre grid
#define LDE     136                 // padded image row (bf16 elems): 272B
#define LDB     (LDE * 2)
#define IMG_BYTES (DIM * LDE * 2)   // W image: 128 rows -> 34816
#define IMG_U4    (IMG_BYTES / 16)

// gemm smem layout (bytes). A buffer = hi(17408) + lo(17408) = 34816.
#define A_LO    17408
#define S_A0    0
#define S_A1    34816
#define S_WHI   69632
#define S_WLO   104448
#define S_BIAS  139264              // float[8][128] = 4096 (all types)
#define S_ROWS  143360              // int[2][64] = 512
#define S_TOTAL 143872

// ---------------- device globals ----------------
__device__ int g_bcount[TT * NB];
__device__ int g_bbase[TT * NB];
__device__ int g_offsets[TT + 1];
__device__ int g_tileBase[TT + 1];
__device__ int g_perm[NMAX];
__device__ __align__(16) uint8_t g_Whi[TT][IMG_BYTES];
__device__ __align__(16) uint8_t g_Wlo[TT][IMG_BYTES];

// ---------------- helpers ----------------
__device__ __forceinline__ uint32_t smem_u32(const void* p) {
    uint32_t a;
    asm("{ .reg .u64 t; cvta.to.shared.u64 t, %1; cvt.u32.u64 %0, t; }" : "=r"(a) : "l"(p));
    return a;
}
__device__ __forceinline__ void ldsm4(uint32_t (&r)[4], uint32_t addr) {
    asm volatile("ldmatrix.sync.aligned.m8n8.x4.shared.b16 {%0,%1,%2,%3}, [%4];"
                 : "=r"(r[0]), "=r"(r[1]), "=r"(r[2]), "=r"(r[3]) : "r"(addr));
}
__device__ __forceinline__ void mma16816(float (&c)[4], const uint32_t (&a)[4],
                                         uint32_t b0, uint32_t b1) {
    asm volatile("mma.sync.aligned.m16n8k16.row.col.f32.bf16.bf16.f32 "
                 "{%0,%1,%2,%3}, {%4,%5,%6,%7}, {%8,%9}, {%0,%1,%2,%3};"
                 : "+f"(c[0]), "+f"(c[1]), "+f"(c[2]), "+f"(c[3])
                 : "r"(a[0]), "r"(a[1]), "r"(a[2]), "r"(a[3]), "r"(b0), "r"(b1));
}
__device__ __forceinline__ uint32_t pkbf(__nv_bfloat16 a, __nv_bfloat16 b) {
    return (uint32_t)__bfloat16_as_ushort(a) | ((uint32_t)__bfloat16_as_ushort(b) << 16);
}

// ---------------- pre: count (blocks 0..NB-1) + W prep (blocks NB..NB+31) ----------------
__global__ void k_pre(const int* __restrict__ xt, const float* __restrict__ W,
                      int n, int seg) {
    __shared__ float ws[32][129];
    const int tid = threadIdx.x, lane = tid & 31;

    if (blockIdx.x < NB) {
        const int bid = blockIdx.x;
        const int start = bid * seg, end = min(start + seg, n);
        __shared__ int cnt[TT];
        if (tid < TT) cnt[tid] = 0;
        __syncthreads();
        int rc[TT];
        #pragma unroll
        for (int t = 0; t < TT; t++) rc[t] = 0;
        const int rounds = (seg + BT - 1) / BT;
        for (int r = 0; r < rounds; r++) {
            int i = start + r * BT + tid;
            int m = (i < end) ? xt[i] : -1;
            #pragma unroll
            for (int t = 0; t < TT; t++)
                rc[t] += __popc(__ballot_sync(0xffffffffu, m == t));
        }
        if (lane == 0) {
            #pragma unroll
            for (int t = 0; t < TT; t++) atomicAdd(&cnt[t], rc[t]);
        }
        __syncthreads();
        if (tid < TT) g_bcount[tid * NB + bid] = cnt[tid];
    } else {
        const int sl = blockIdx.x - NB;
        const int t  = sl >> 2;
        const int kb = (sl & 3) * 32;
        #pragma unroll
        for (int j = 0; j < 16; j++) {
            int idx = tid + j * 256;
            int r = idx >> 7, col = idx & 127;
            ws[r][col] = W[((size_t)t * DIM + kb + r) * DIM + col];
        }
        __syncthreads();
        const int kk = tid & 15;
        #pragma unroll
        for (int j = 0; j < 8; j++) {
            int nn = (tid >> 4) + j * 16;
            float w0 = ws[2 * kk][nn], w1 = ws[2 * kk + 1][nn];
            __nv_bfloat16 h0 = __float2bfloat16_rn(w0), h1 = __float2bfloat16_rn(w1);
            __nv_bfloat16 l0 = __float2bfloat16_rn(w0 - __bfloat162float(h0));
            __nv_bfloat16 l1 = __float2bfloat16_rn(w1 - __bfloat162float(h1));
            uint32_t off = (uint32_t)nn * LDB + (uint32_t)(kb + 2 * kk) * 2;
            *(uint32_t*)(g_Whi[t] + off) = pkbf(h0, h1);
            *(uint32_t*)(g_Wlo[t] + off) = pkbf(l0, l1);
        }
    }
}

__global__ void k_scan() {
    const int tid = threadIdx.x, warp = tid >> 5, lane = tid & 31;
    __shared__ int tot[TT];
    if (warp < TT) {
        int s = 0;
        #pragma unroll
        for (int c = 0; c < NB / 32; c++) s += g_bcount[warp * NB + c * 32 + lane];
        #pragma unroll
        for (int o = 16; o; o >>= 1) s += __shfl_xor_sync(0xffffffffu, s, o);
        if (lane == 0) tot[warp] = s;
    }
    __syncthreads();
    if (tid == 0) {
        int o = 0, tbv = 0;
        g_offsets[0] = 0; g_tileBase[0] = 0;
        for (int t = 0; t < TT; t++) {
            o += tot[t];
            g_offsets[t + 1] = o;
            tbv += (tot[t] + TILE_M - 1) / TILE_M;
            g_tileBase[t + 1] = tbv;
        }
    }
    __syncthreads();
    if (warp < TT) {
        int run = g_offsets[warp];
        #pragma unroll
        for (int c = 0; c < NB / 32; c++) {
            int v = g_bcount[warp * NB + c * 32 + lane];
            int xsc = v;
            #pragma unroll
            for (int o = 1; o < 32; o <<= 1) {
                int y = __shfl_up_sync(0xffffffffu, xsc, o);
                if (lane >= o) xsc += y;
            }
            g_bbase[warp * NB + c * 32 + lane] = run + xsc - v;
            run += __shfl_sync(0xffffffffu, xsc, 31);
        }
    }
}

__global__ void k_scatter(const int* __restrict__ xt, int n, int seg) {
    const int bid = blockIdx.x, tid = threadIdx.x, lane = tid & 31;
    const int start = bid * seg, end = min(start + seg, n);
    __shared__ int cur[TT];
    if (tid < TT) cur[tid] = g_bbase[tid * NB + bid];
    __syncthreads();
    const int rounds = (seg + BT - 1) / BT;
    for (int r = 0; r < rounds; r++) {
        int i = start + r * BT + tid;
        int m = (i < end) ? xt[i] : -1;
        #pragma unroll
        for (int t = 0; t < TT; t++) {
            unsigned mask = __ballot_sync(0xffffffffu, m == t);
            if (mask) {
                int leader = __ffs(mask) - 1;
                int pos = 0;
                if (lane == leader) pos = atomicAdd(&cur[t], __popc(mask));
                pos = __shfl_sync(0xffffffffu, pos, leader);
                if (m == t) g_perm[pos + __popc(mask & ((1u << lane) - 1u))] = i;
            }
        }
    }
}

// ---------------- GEMM ----------------
__device__ __forceinline__ void copyW(int t, uint8_t* smem, int tid) {
    const uint4* shi = (const uint4*)g_Whi[t];
    const uint4* slo = (const uint4*)g_Wlo[t];
    uint4* dhi = (uint4*)(smem + S_WHI);
    uint4* dlo = (uint4*)(smem + S_WLO);
    #pragma unroll 4
    for (int i = tid; i < IMG_U4; i += GT) { dhi[i] = shi[i]; dlo[i] = slo[i]; }
}

// convert+store one x row (512B, lane-sliced) into hi/lo halves of an A buffer
__device__ __forceinline__ void cvtRow(uint4 vv, uint8_t* dst, int ir, int lane) {
    float4 f = *(const float4*)&vv;
    __nv_bfloat16 h0 = __float2bfloat16_rn(f.x), h1 = __float2bfloat16_rn(f.y);
    __nv_bfloat16 h2 = __float2bfloat16_rn(f.z), h3 = __float2bfloat16_rn(f.w);
    __nv_bfloat16 l0 = __float2bfloat16_rn(f.x - __bfloat162float(h0));
    __nv_bfloat16 l1 = __float2bfloat16_rn(f.y - __bfloat162float(h1));
    __nv_bfloat16 l2 = __float2bfloat16_rn(f.z - __bfloat162float(h2));
    __nv_bfloat16 l3 = __float2bfloat16_rn(f.w - __bfloat162float(h3));
    uint32_t offB = (uint32_t)ir * LDB + (uint32_t)lane * 8;
    *(uint2*)(dst + offB)        = make_uint2(pkbf(h0, h1), pkbf(h2, h3));
    *(uint2*)(dst + A_LO + offB) = make_uint2(pkbf(l0, l1), pkbf(l2, l3));
}

__global__ __launch_bounds__(GT, 1)
void k_gemm(const float* __restrict__ x,
            const float* __restrict__ b,
            float* __restrict__ out)
{
    extern __shared__ uint8_t smem[];
    const int tid  = threadIdx.x;
    const int warp = tid >> 5;
    const int lane = tid & 31;
    const bool consumer = (warp < 8);
    const int mw = warp & 1;        // consumer: m chunk of 32 rows (0..1)
    const int nq = warp >> 1;       // consumer: n quarter of 32 cols (0..3)
    const int pw = warp - 8;        // producer index 0..7

    const uint32_t sbase = smem_u32(smem);
    float* biasAll = (float*)(smem + S_BIAS);   // [8][128]
    int*   rowsS   = (int*)(smem + S_ROWS);     // [2][64]

    int tb[TT + 1], off[TT + 1];
    #pragma unroll
    for (int i = 0; i <= TT; i++) { tb[i] = g_tileBase[i]; off[i] = g_offsets[i]; }

    const int total = tb[TT];
    const int per   = (total + gridDim.x - 1) / gridDim.x;
    const int i0    = blockIdx.x * per;
    const int i1    = min(i0 + per, total);
    if (i0 >= i1) return;

    // consumer ldmatrix lane offsets (mapping proven R3-R13)
    const uint32_t aOff = (uint32_t)(mw * 32 + (lane & 15)) * LDB + (uint32_t)(lane >> 4) * 16;
    const uint32_t bOff = (uint32_t)(nq * 32 + (lane & 7) + ((lane & 16) ? 8 : 0)) * LDB
                        + (uint32_t)((lane >> 3) & 1) * 16;

    float acc[2][4][4];
    #pragma unroll
    for (int s = 0; s < 2; s++)
        #pragma unroll
        for (int j = 0; j < 4; j++)
            #pragma unroll
            for (int q = 0; q < 4; q++) acc[s][j][q] = 0.f;

    int cur_type;
    int rown = -1;          // producer: perm indices (lane<8) for NEXT staged tile
    uint4 v[8];             // producer: raw x rows for NEXT staged tile (held)

    // ---- prologue ----
    {
        int t = 0;
        #pragma unroll
        for (int s = 1; s < TT; s++) t += (i0 >= tb[s]);
        cur_type = t;
        copyW(t, smem, tid);
        // all biases into smem once
        for (int c = tid; c < TT * DIM; c += GT) biasAll[c] = b[c];

        if (!consumer) {
            // stage tile i0 synchronously
            int segStart = off[t] + (i0 - tb[t]) * TILE_M;
            int nr       = min(TILE_M, off[t + 1] - segStart);
            int r0 = -1;
            if (lane < 8) {
                int idx = pw * 8 + lane;
                r0 = (idx < nr) ? g_perm[segStart + idx] : -1;
                rowsS[(i0 & 1) * TILE_M + idx] = r0;
            }
            uint8_t* dst = smem + ((i0 & 1) ? S_A1 : S_A0);
            #pragma unroll
            for (int rr = 0; rr < 8; rr++) {
                int row = __shfl_sync(0xffffffffu, r0, rr);
                uint4 vv = make_uint4(0, 0, 0, 0);
                if (row >= 0) vv = ((const uint4*)x)[(size_t)row * 32 + lane];
                cvtRow(vv, dst, pw * 8 + rr, lane);
            }
            // preload tile i0+1 into held regs
            rown = -1;
            #pragma unroll
            for (int rr = 0; rr < 8; rr++) v[rr] = make_uint4(0, 0, 0, 0);
            if (i0 + 1 < i1) {
                int nt1 = 0;
                #pragma unroll
                for (int s = 1; s < TT; s++) nt1 += ((i0 + 1) >= tb[s]);
                int ss = off[nt1] + (i0 + 1 - tb[nt1]) * TILE_M;
                int nr1 = min(TILE_M, off[nt1 + 1] - ss);
                if (lane < 8) {
                    int idx = pw * 8 + lane;
                    rown = (idx < nr1) ? g_perm[ss + idx] : -1;
                }
                #pragma unroll
                for (int rr = 0; rr < 8; rr++) {
                    int row = __shfl_sync(0xffffffffu, rown, rr);
                    if (row >= 0) v[rr] = ((const uint4*)x)[(size_t)row * 32 + lane];
                }
            }
        }
        __syncthreads();
    }

    for (int i = i0; i < i1; i++) {
        const int cb = i & 1;
        int nt = cur_type;                    // type of tile i+1 (uniform)
        if (i + 1 < i1) {
            nt = 0;
            #pragma unroll
            for (int s = 1; s < TT; s++) nt += ((i + 1) >= tb[s]);
        }

        if (consumer) {
            int t = 0;                        // this tile's type (for bias)
            #pragma unroll
            for (int s = 1; s < TT; s++) t += (i >= tb[s]);
            // ---- MMA: single kk loop, hi/lo fragments shared across products ----
            // products into the same acc: a_hi*b_hi + a_hi*b_lo + a_lo*b_hi
            {
                const uint32_t aHi = sbase + (cb ? S_A1 : S_A0) + aOff;
                const uint32_t aLo = aHi + A_LO;
                const uint32_t bHi = sbase + S_WHI + bOff;
                const uint32_t bLo = sbase + S_WLO + bOff;
                #pragma unroll
                for (int kk = 0; kk < 8; kk++) {
                    const uint32_t ko = kk * 32;
                    uint32_t ah0[4], ah1[4], al0[4], al1[4];
                    uint32_t bh0[4], bh1[4], bl0[4], bl1[4];
                    ldsm4(ah0, aHi + ko);
                    ldsm4(ah1, aHi + 16 * LDB + ko);
                    ldsm4(bh0, bHi + ko);
                    ldsm4(bh1, bHi + 16 * LDB + ko);
                    ldsm4(al0, aLo + ko);
                    ldsm4(al1, aLo + 16 * LDB + ko);
                    ldsm4(bl0, bLo + ko);
                    ldsm4(bl1, bLo + 16 * LDB + ko);
                    // p0: hi x hi
                    mma16816(acc[0][0], ah0, bh0[0], bh0[1]);
                    mma16816(acc[0][1], ah0, bh0[2], bh0[3]);
                    mma16816(acc[0][2], ah0, bh1[0], bh1[1]);
                    mma16816(acc[0][3], ah0, bh1[2], bh1[3]);
                    mma16816(acc[1][0], ah1, bh0[0], bh0[1]);
                    mma16816(acc[1][1], ah1, bh0[2], bh0[3]);
                    mma16816(acc[1][2], ah1, bh1[0], bh1[1]);
                    mma16816(acc[1][3], ah1, bh1[2], bh1[3]);
                    // p1: hi x lo
                    mma16816(acc[0][0], ah0, bl0[0], bl0[1]);
                    mma16816(acc[0][1], ah0, bl0[2], bl0[3]);
                    mma16816(acc[0][2], ah0, bl1[0], bl1[1]);
                    mma16816(acc[0][3], ah0, bl1[2], bl1[3]);
                    mma16816(acc[1][0], ah1, bl0[0], bl0[1]);
                    mma16816(acc[1][1], ah1, bl0[2], bl0[3]);
                    mma16816(acc[1][2], ah1, bl1[0], bl1[1]);
                    mma16816(acc[1][3], ah1, bl1[2], bl1[3]);
                    // p2: lo x hi
                    mma16816(acc[0][0], al0, bh0[0], bh0[1]);
                    mma16816(acc[0][1], al0, bh0[2], bh0[3]);
                    mma16816(acc[0][2], al0, bh1[0], bh1[1]);
                    mma16816(acc[0][3], al0, bh1[2], bh1[3]);
                    mma16816(acc[1][0], al1, bh0[0], bh0[1]);
                    mma16816(acc[1][1], al1, bh0[2], bh0[3]);
                    mma16816(acc[1][2], al1, bh1[0], bh1[1]);
                    mma16816(acc[1][3], al1, bh1[2], bh1[3]);
                }
            }
            // ---- epilogue (rowsS slot cb stable until the barrier) ----
            const int g = lane >> 2;
            const float* bS = biasAll + t * DIM;
            #pragma unroll
            for (int s = 0; s < 2; s++) {
                const int rbase = mw * 32 + s * 16 + g;
                const int r1 = rowsS[cb * TILE_M + rbase];
                const int r2 = rowsS[cb * TILE_M + rbase + 8];
                #pragma unroll
                for (int j = 0; j < 4; j++) {
                    int col = nq * 32 + j * 8 + (lane & 3) * 2;
                    float2 bb = *(const float2*)(bS + col);
                    if (r1 >= 0)
                        *(float2*)(out + (size_t)r1 * DIM + col) =
                            make_float2(acc[s][j][0] + bb.x, acc[s][j][1] + bb.y);
                    if (r2 >= 0)
                        *(float2*)(out + (size_t)r2 * DIM + col) =
                            make_float2(acc[s][j][2] + bb.x, acc[s][j][3] + bb.y);
                    acc[s][j][0] = acc[s][j][1] = acc[s][j][2] = acc[s][j][3] = 0.f;
                }
            }
        } else {
            // ---- producer: convert held tile i+1, then load tile i+2 ----
            if (i + 1 < i1) {
                uint8_t* dst = smem + ((cb ^ 1) ? S_A1 : S_A0);
                #pragma unroll
                for (int rr = 0; rr < 8; rr++)
                    cvtRow(v[rr], dst, pw * 8 + rr, lane);
                if (lane < 8)
                    rowsS[(cb ^ 1) * TILE_M + pw * 8 + lane] = rown;
            }
            asm volatile("" ::: "memory");   // keep loads below converts
            rown = -1;
            #pragma unroll
            for (int rr = 0; rr < 8; rr++) v[rr] = make_uint4(0, 0, 0, 0);
            if (i + 2 < i1) {
                int nt2 = 0;
                #pragma unroll
                for (int s = 1; s < TT; s++) nt2 += ((i + 2) >= tb[s]);
                int ss = off[nt2] + (i + 2 - tb[nt2]) * TILE_M;
                int nr2 = min(TILE_M, off[nt2 + 1] - ss);
                if (lane < 8) {
                    int idx = pw * 8 + lane;
                    rown = (idx < nr2) ? g_perm[ss + idx] : -1;
                }
                #pragma unroll
                for (int rr = 0; rr < 8; rr++) {
                    int row = __shfl_sync(0xffffffffu, rown, rr);
                    if (row >= 0) v[rr] = ((const uint4*)x)[(size_t)row * 32 + lane];
                }
            }
        }

        __syncthreads();
        if (nt != cur_type) {     // rare W reload (type boundary)
            copyW(nt, smem, tid);
            cur_type = nt;
            __syncthreads();
        }
    }
}

// ---------------- launch ----------------
extern "C" void kernel_launch(void* const* d_in, const int* in_sizes, int n_in,
                              void* d_out, int out_size)
{
    const float* x      = (const float*)d_in[0];
    const int*   x_type = (const int*)d_in[1];
    const float* W      = (const float*)d_in[2];
    const float* b      = (const float*)d_in[3];
    float*       out    = (float*)d_out;

    const int N   = in_sizes[1];
    const int seg = (N + NB - 1) / NB;

    static int nsm = 0;
    if (!nsm) {
        cudaDeviceGetAttribute(&nsm, cudaDevAttrMultiProcessorCount, 0);
        if (nsm <= 0) nsm = 148;
        cudaFuncSetAttribute(k_gemm, cudaFuncAttributeMaxDynamicSharedMemorySize, S_TOTAL);
    }

    k_pre<<<NB + PREPB, BT>>>(x_type, W, N, seg);
    k_scan<<<1, 256>>>();
    k_scatter<<<NB, BT>>>(x_type, N, seg);
    k_gemm<<<nsm, GT, S_TOTAL>>>(x, b, out);
}

// round 15
// speedup vs baseline: 1.3302x; 1.3302x over previous
#include <cuda_runtime.h>
#include <cuda_fp16.h>
#include <cstdint>

// HeteLinear: out[n] = x[n] @ W[x_type[n]] + b[x_type[n]]
// N=262144, IN=OUT=128, T=8, fp32.
// Grouped GEMM on mma.sync HMMA, persistent producer/consumer CTAs.
// R15: 2-PRODUCT FP16 SPLIT: x = x_hi(fp16) + x_lo(fp16)  (x error ~2^-21),
// W as a SINGLE fp16 image (rel err 2^-11 -> aggregate ~2.8e-4 < 1e-3).
// out = x_hi*W + x_lo*W : mma/warp-tile 192 -> 128, ldsm 64 -> 48, and the
// legacy-HMMA pipe demand (measured ~12cyc/mma occupancy) drops 33%.

#define NMAX    262144
#define TT      8
#define DIM     128
#define TILE_M  64
#define GT      512
#define NB      256                 // compaction blocks
#define BT      256
#define PREPB   32                  // prep blocks appended to k_pre grid
#define LDE     136                 // padded image row (fp16 elems): 272B
#define LDB     (LDE * 2)
#define IMG_BYTES (DIM * LDE * 2)   // image: 128 rows -> 34816
#define IMG_U4    (IMG_BYTES / 16)

// gemm smem layout (bytes). A buffer = hi(17408) + lo(17408) = 34816.
#define A_LO    17408
#define S_A0    0
#define S_A1    34816
#define S_W     69632               // single fp16 W image (34816)
#define S_BIAS  104448              // float[8][128] = 4096 (all types)
#define S_ROWS  108544              // int[2][64] = 512
#define S_TOTAL 109056

// ---------------- device globals ----------------
__device__ int g_bcount[TT * NB];
__device__ int g_bbase[TT * NB];
__device__ int g_offsets[TT + 1];
__device__ int g_tileBase[TT + 1];
__device__ int g_perm[NMAX];
__device__ __align__(16) uint8_t g_W[TT][IMG_BYTES];

// ---------------- helpers ----------------
__device__ __forceinline__ uint32_t smem_u32(const void* p) {
    uint32_t a;
    asm("{ .reg .u64 t; cvta.to.shared.u64 t, %1; cvt.u32.u64 %0, t; }" : "=r"(a) : "l"(p));
    return a;
}
__device__ __forceinline__ void ldsm4(uint32_t (&r)[4], uint32_t addr) {
    asm volatile("ldmatrix.sync.aligned.m8n8.x4.shared.b16 {%0,%1,%2,%3}, [%4];"
                 : "=r"(r[0]), "=r"(r[1]), "=r"(r[2]), "=r"(r[3]) : "r"(addr));
}
__device__ __forceinline__ void mma16816(float (&c)[4], const uint32_t (&a)[4],
                                         uint32_t b0, uint32_t b1) {
    asm volatile("mma.sync.aligned.m16n8k16.row.col.f32.f16.f16.f32 "
                 "{%0,%1,%2,%3}, {%4,%5,%6,%7}, {%8,%9}, {%0,%1,%2,%3};"
                 : "+f"(c[0]), "+f"(c[1]), "+f"(c[2]), "+f"(c[3])
                 : "r"(a[0]), "r"(a[1]), "r"(a[2]), "r"(a[3]), "r"(b0), "r"(b1));
}
__device__ __forceinline__ uint32_t pkh(__half a, __half b) {
    return (uint32_t)__half_as_ushort(a) | ((uint32_t)__half_as_ushort(b) << 16);
}

// ---------------- pre: count (blocks 0..NB-1) + W prep (blocks NB..NB+31) ----------------
__global__ void k_pre(const int* __restrict__ xt, const float* __restrict__ W,
                      int n, int seg) {
    __shared__ float ws[32][129];
    const int tid = threadIdx.x, lane = tid & 31;

    if (blockIdx.x < NB) {
        const int bid = blockIdx.x;
        const int start = bid * seg, end = min(start + seg, n);
        __shared__ int cnt[TT];
        if (tid < TT) cnt[tid] = 0;
        __syncthreads();
        int rc[TT];
        #pragma unroll
        for (int t = 0; t < TT; t++) rc[t] = 0;
        const int rounds = (seg + BT - 1) / BT;
        for (int r = 0; r < rounds; r++) {
            int i = start + r * BT + tid;
            int m = (i < end) ? xt[i] : -1;
            #pragma unroll
            for (int t = 0; t < TT; t++)
                rc[t] += __popc(__ballot_sync(0xffffffffu, m == t));
        }
        if (lane == 0) {
            #pragma unroll
            for (int t = 0; t < TT; t++) atomicAdd(&cnt[t], rc[t]);
        }
        __syncthreads();
        if (tid < TT) g_bcount[tid * NB + bid] = cnt[tid];
    } else {
        // W prep slice: type t, k-chunk kb (32 rows), single fp16 image
        const int sl = blockIdx.x - NB;
        const int t  = sl >> 2;
        const int kb = (sl & 3) * 32;
        #pragma unroll
        for (int j = 0; j < 16; j++) {
            int idx = tid + j * 256;
            int r = idx >> 7, col = idx & 127;
            ws[r][col] = W[((size_t)t * DIM + kb + r) * DIM + col];
        }
        __syncthreads();
        const int kk = tid & 15;
        #pragma unroll
        for (int j = 0; j < 8; j++) {
            int nn = (tid >> 4) + j * 16;
            float w0 = ws[2 * kk][nn], w1 = ws[2 * kk + 1][nn];
            uint32_t off = (uint32_t)nn * LDB + (uint32_t)(kb + 2 * kk) * 2;
            *(uint32_t*)(g_W[t] + off) = pkh(__float2half_rn(w0), __float2half_rn(w1));
        }
    }
}

__global__ void k_scan() {
    const int tid = threadIdx.x, warp = tid >> 5, lane = tid & 31;
    __shared__ int tot[TT];
    if (warp < TT) {
        int s = 0;
        #pragma unroll
        for (int c = 0; c < NB / 32; c++) s += g_bcount[warp * NB + c * 32 + lane];
        #pragma unroll
        for (int o = 16; o; o >>= 1) s += __shfl_xor_sync(0xffffffffu, s, o);
        if (lane == 0) tot[warp] = s;
    }
    __syncthreads();
    if (tid == 0) {
        int o = 0, tbv = 0;
        g_offsets[0] = 0; g_tileBase[0] = 0;
        for (int t = 0; t < TT; t++) {
            o += tot[t];
            g_offsets[t + 1] = o;
            tbv += (tot[t] + TILE_M - 1) / TILE_M;
            g_tileBase[t + 1] = tbv;
        }
    }
    __syncthreads();
    if (warp < TT) {
        int run = g_offsets[warp];
        #pragma unroll
        for (int c = 0; c < NB / 32; c++) {
            int v = g_bcount[warp * NB + c * 32 + lane];
            int xsc = v;
            #pragma unroll
            for (int o = 1; o < 32; o <<= 1) {
                int y = __shfl_up_sync(0xffffffffu, xsc, o);
                if (lane >= o) xsc += y;
            }
            g_bbase[warp * NB + c * 32 + lane] = run + xsc - v;
            run += __shfl_sync(0xffffffffu, xsc, 31);
        }
    }
}

__global__ void k_scatter(const int* __restrict__ xt, int n, int seg) {
    const int bid = blockIdx.x, tid = threadIdx.x, lane = tid & 31;
    const int start = bid * seg, end = min(start + seg, n);
    __shared__ int cur[TT];
    if (tid < TT) cur[tid] = g_bbase[tid * NB + bid];
    __syncthreads();
    const int rounds = (seg + BT - 1) / BT;
    for (int r = 0; r < rounds; r++) {
        int i = start + r * BT + tid;
        int m = (i < end) ? xt[i] : -1;
        #pragma unroll
        for (int t = 0; t < TT; t++) {
            unsigned mask = __ballot_sync(0xffffffffu, m == t);
            if (mask) {
                int leader = __ffs(mask) - 1;
                int pos = 0;
                if (lane == leader) pos = atomicAdd(&cur[t], __popc(mask));
                pos = __shfl_sync(0xffffffffu, pos, leader);
                if (m == t) g_perm[pos + __popc(mask & ((1u << lane) - 1u))] = i;
            }
        }
    }
}

// ---------------- GEMM ----------------
__device__ __forceinline__ void copyW(int t, uint8_t* smem, int tid) {
    const uint4* sw = (const uint4*)g_W[t];
    uint4* dw = (uint4*)(smem + S_W);
    #pragma unroll 4
    for (int i = tid; i < IMG_U4; i += GT) dw[i] = sw[i];
}

// convert+store one x row (512B, lane-sliced) into fp16 hi/lo halves of an A buffer
__device__ __forceinline__ void cvtRow(uint4 vv, uint8_t* dst, int ir, int lane) {
    float4 f = *(const float4*)&vv;
    __half h0 = __float2half_rn(f.x), h1 = __float2half_rn(f.y);
    __half h2 = __float2half_rn(f.z), h3 = __float2half_rn(f.w);
    __half l0 = __float2half_rn(f.x - __half2float(h0));
    __half l1 = __float2half_rn(f.y - __half2float(h1));
    __half l2 = __float2half_rn(f.z - __half2float(h2));
    __half l3 = __float2half_rn(f.w - __half2float(h3));
    uint32_t offB = (uint32_t)ir * LDB + (uint32_t)lane * 8;
    *(uint2*)(dst + offB)        = make_uint2(pkh(h0, h1), pkh(h2, h3));
    *(uint2*)(dst + A_LO + offB) = make_uint2(pkh(l0, l1), pkh(l2, l3));
}

__global__ __launch_bounds__(GT, 1)
void k_gemm(const float* __restrict__ x,
            const float* __restrict__ b,
            float* __restrict__ out)
{
    extern __shared__ uint8_t smem[];
    const int tid  = threadIdx.x;
    const int warp = tid >> 5;
    const int lane = tid & 31;
    const bool consumer = (warp < 8);
    const int mw = warp & 1;        // consumer: m chunk of 32 rows (0..1)
    const int nq = warp >> 1;       // consumer: n quarter of 32 cols (0..3)
    const int pw = warp - 8;        // producer index 0..7

    const uint32_t sbase = smem_u32(smem);
    float* biasAll = (float*)(smem + S_BIAS);   // [8][128]
    int*   rowsS   = (int*)(smem + S_ROWS);     // [2][64]

    int tb[TT + 1], off[TT + 1];
    #pragma unroll
    for (int i = 0; i <= TT; i++) { tb[i] = g_tileBase[i]; off[i] = g_offsets[i]; }

    const int total = tb[TT];
    const int per   = (total + gridDim.x - 1) / gridDim.x;
    const int i0    = blockIdx.x * per;
    const int i1    = min(i0 + per, total);
    if (i0 >= i1) return;

    // consumer ldmatrix lane offsets (mapping proven R3-R14)
    const uint32_t aOff = (uint32_t)(mw * 32 + (lane & 15)) * LDB + (uint32_t)(lane >> 4) * 16;
    const uint32_t bOff = (uint32_t)(nq * 32 + (lane & 7) + ((lane & 16) ? 8 : 0)) * LDB
                        + (uint32_t)((lane >> 3) & 1) * 16;

    float acc[2][4][4];
    #pragma unroll
    for (int s = 0; s < 2; s++)
        #pragma unroll
        for (int j = 0; j < 4; j++)
            #pragma unroll
            for (int q = 0; q < 4; q++) acc[s][j][q] = 0.f;

    int cur_type;
    int rown = -1;          // producer: perm indices (lane<8) for NEXT staged tile
    uint4 v[8];             // producer: raw x rows for NEXT staged tile (held)

    // ---- prologue ----
    {
        int t = 0;
        #pragma unroll
        for (int s = 1; s < TT; s++) t += (i0 >= tb[s]);
        cur_type = t;
        copyW(t, smem, tid);
        // all biases into smem once
        for (int c = tid; c < TT * DIM; c += GT) biasAll[c] = b[c];

        if (!consumer) {
            // stage tile i0 synchronously
            int segStart = off[t] + (i0 - tb[t]) * TILE_M;
            int nr       = min(TILE_M, off[t + 1] - segStart);
            int r0 = -1;
            if (lane < 8) {
                int idx = pw * 8 + lane;
                r0 = (idx < nr) ? g_perm[segStart + idx] : -1;
                rowsS[(i0 & 1) * TILE_M + idx] = r0;
            }
            uint8_t* dst = smem + ((i0 & 1) ? S_A1 : S_A0);
            #pragma unroll
            for (int rr = 0; rr < 8; rr++) {
                int row = __shfl_sync(0xffffffffu, r0, rr);
                uint4 vv = make_uint4(0, 0, 0, 0);
                if (row >= 0) vv = ((const uint4*)x)[(size_t)row * 32 + lane];
                cvtRow(vv, dst, pw * 8 + rr, lane);
            }
            // preload tile i0+1 into held regs
            rown = -1;
            #pragma unroll
            for (int rr = 0; rr < 8; rr++) v[rr] = make_uint4(0, 0, 0, 0);
            if (i0 + 1 < i1) {
                int nt1 = 0;
                #pragma unroll
                for (int s = 1; s < TT; s++) nt1 += ((i0 + 1) >= tb[s]);
                int ss = off[nt1] + (i0 + 1 - tb[nt1]) * TILE_M;
                int nr1 = min(TILE_M, off[nt1 + 1] - ss);
                if (lane < 8) {
                    int idx = pw * 8 + lane;
                    rown = (idx < nr1) ? g_perm[ss + idx] : -1;
                }
                #pragma unroll
                for (int rr = 0; rr < 8; rr++) {
                    int row = __shfl_sync(0xffffffffu, rown, rr);
                    if (row >= 0) v[rr] = ((const uint4*)x)[(size_t)row * 32 + lane];
                }
            }
        }
        __syncthreads();
    }

    for (int i = i0; i < i1; i++) {
        const int cb = i & 1;
        int nt = cur_type;                    // type of tile i+1 (uniform)
        if (i + 1 < i1) {
            nt = 0;
            #pragma unroll
            for (int s = 1; s < TT; s++) nt += ((i + 1) >= tb[s]);
        }

        if (consumer) {
            int t = 0;                        // this tile's type (for bias)
            #pragma unroll
            for (int s = 1; s < TT; s++) t += (i >= tb[s]);
            // ---- MMA: 2 fp16 products (x_hi*W + x_lo*W), shared W fragments ----
            {
                const uint32_t aHi = sbase + (cb ? S_A1 : S_A0) + aOff;
                const uint32_t aLo = aHi + A_LO;
                const uint32_t bW  = sbase + S_W + bOff;
                #pragma unroll
                for (int kk = 0; kk < 8; kk++) {
                    const uint32_t ko = kk * 32;
                    uint32_t ah0[4], ah1[4], al0[4], al1[4];
                    uint32_t bw0[4], bw1[4];
                    ldsm4(ah0, aHi + ko);
                    ldsm4(ah1, aHi + 16 * LDB + ko);
                    ldsm4(bw0, bW + ko);
                    ldsm4(bw1, bW + 16 * LDB + ko);
                    ldsm4(al0, aLo + ko);
                    ldsm4(al1, aLo + 16 * LDB + ko);
                    // p0: hi x W
                    mma16816(acc[0][0], ah0, bw0[0], bw0[1]);
                    mma16816(acc[0][1], ah0, bw0[2], bw0[3]);
                    mma16816(acc[0][2], ah0, bw1[0], bw1[1]);
                    mma16816(acc[0][3], ah0, bw1[2], bw1[3]);
                    mma16816(acc[1][0], ah1, bw0[0], bw0[1]);
                    mma16816(acc[1][1], ah1, bw0[2], bw0[3]);
                    mma16816(acc[1][2], ah1, bw1[0], bw1[1]);
                    mma16816(acc[1][3], ah1, bw1[2], bw1[3]);
                    // p1: lo x W
                    mma16816(acc[0][0], al0, bw0[0], bw0[1]);
                    mma16816(acc[0][1], al0, bw0[2], bw0[3]);
                    mma16816(acc[0][2], al0, bw1[0], bw1[1]);
                    mma16816(acc[0][3], al0, bw1[2], bw1[3]);
                    mma16816(acc[1][0], al1, bw0[0], bw0[1]);
                    mma16816(acc[1][1], al1, bw0[2], bw0[3]);
                    mma16816(acc[1][2], al1, bw1[0], bw1[1]);
                    mma16816(acc[1][3], al1, bw1[2], bw1[3]);
                }
            }
            // ---- epilogue (rowsS slot cb stable until the barrier) ----
            const int g = lane >> 2;
            const float* bS = biasAll + t * DIM;
            #pragma unroll
            for (int s = 0; s < 2; s++) {
                const int rbase = mw * 32 + s * 16 + g;
                const int r1 = rowsS[cb * TILE_M + rbase];
                const int r2 = rowsS[cb * TILE_M + rbase + 8];
                #pragma unroll
                for (int j = 0; j < 4; j++) {
                    int col = nq * 32 + j * 8 + (lane & 3) * 2;
                    float2 bb = *(const float2*)(bS + col);
                    if (r1 >= 0)
                        *(float2*)(out + (size_t)r1 * DIM + col) =
                            make_float2(acc[0][j][0] * 0.f + acc[s][j][0] + bb.x,
                                        acc[s][j][1] + bb.y);
                    if (r2 >= 0)
                        *(float2*)(out + (size_t)r2 * DIM + col) =
                            make_float2(acc[s][j][2] + bb.x, acc[s][j][3] + bb.y);
                    acc[s][j][0] = acc[s][j][1] = acc[s][j][2] = acc[s][j][3] = 0.f;
                }
            }
        } else {
            // ---- producer: convert held tile i+1, then load tile i+2 ----
            if (i + 1 < i1) {
                uint8_t* dst = smem + ((cb ^ 1) ? S_A1 : S_A0);
                #pragma unroll
                for (int rr = 0; rr < 8; rr++)
                    cvtRow(v[rr], dst, pw * 8 + rr, lane);
                if (lane < 8)
                    rowsS[(cb ^ 1) * TILE_M + pw * 8 + lane] = rown;
            }
            asm volatile("" ::: "memory");   // keep loads below converts
            rown = -1;
            #pragma unroll
            for (int rr = 0; rr < 8; rr++) v[rr] = make_uint4(0, 0, 0, 0);
            if (i + 2 < i1) {
                int nt2 = 0;
                #pragma unroll
                for (int s = 1; s < TT; s++) nt2 += ((i + 2) >= tb[s]);
                int ss = off[nt2] + (i + 2 - tb[nt2]) * TILE_M;
                int nr2 = min(TILE_M, off[nt2 + 1] - ss);
                if (lane < 8) {
                    int idx = pw * 8 + lane;
                    rown = (idx < nr2) ? g_perm[ss + idx] : -1;
                }
                #pragma unroll
                for (int rr = 0; rr < 8; rr++) {
                    int row = __shfl_sync(0xffffffffu, rown, rr);
                    if (row >= 0) v[rr] = ((const uint4*)x)[(size_t)row * 32 + lane];
                }
            }
        }

        __syncthreads();
        if (nt != cur_type) {     // rare W reload (type boundary)
            copyW(nt, smem, tid);
            cur_type = nt;
            __syncthreads();
        }
    }
}

// ---------------- launch ----------------
extern "C" void kernel_launch(void* const* d_in, const int* in_sizes, int n_in,
                              void* d_out, int out_size)
{
    const float* x      = (const float*)d_in[0];
    const int*   x_type = (const int*)d_in[1];
    const float* W      = (const float*)d_in[2];
    const float* b      = (const float*)d_in[3];
    float*       out    = (float*)d_out;

    const int N   = in_sizes[1];
    const int seg = (N + NB - 1) / NB;

    static int nsm = 0;
    if (!nsm) {
        cudaDeviceGetAttribute(&nsm, cudaDevAttrMultiProcessorCount, 0);
        if (nsm <= 0) nsm = 148;
        cudaFuncSetAttribute(k_gemm, cudaFuncAttributeMaxDynamicSharedMemorySize, S_TOTAL);
    }

    k_pre<<<NB + PREPB, BT>>>(x_type, W, N, seg);
    k_scan<<<1, 256>>>();
    k_scatter<<<NB, BT>>>(x_type, N, seg);
    k_gemm<<<nsm, GT, S_TOTAL>>>(x, b, out);
}